// round 8
// baseline (speedup 1.0000x reference)
#include <cuda_runtime.h>
#include <cuda_fp16.h>

#define MAX_NODES 50000
#define MAX_EDGES 800000
#define D 64
#define NBLK 148          // persistent-kernel grid (all co-resident on 148 SMs)

// ---------------------------------------------------------------------------
// Scratch (device globals; no allocation allowed)
// ---------------------------------------------------------------------------
__device__ float   g_lin[MAX_NODES * D];       // data @ W_lin^T + b_lin (fp32)
__device__ __half2 g_lin_h[MAX_NODES * (D/2)]; // fp16 shadow for gather reads
__device__ int     g_deg[MAX_NODES];           // in-degree (re-zeroed each call)
__device__ int     g_off[MAX_NODES];           // CSR row offsets
__device__ int     g_cur[MAX_NODES];           // fill cursors
__device__ int     g_csum[NBLK];               // per-chunk sums
__device__ int     g_elist[MAX_EDGES];         // src ids in CSR order

// Software grid barrier (gen monotonic across calls; cnt returns to 0)
__device__ volatile unsigned g_bar_gen;
__device__ unsigned g_bar_cnt;

__device__ __forceinline__ void grid_bar() {
    __syncthreads();
    if (threadIdx.x == 0) {
        unsigned gen = g_bar_gen;
        __threadfence();
        unsigned prev = atomicAdd(&g_bar_cnt, 1u);
        if (prev == NBLK - 1) {
            g_bar_cnt = 0;
            __threadfence();
            g_bar_gen = gen + 1;
        } else {
            while (g_bar_gen == gen) { __nanosleep(32); }
        }
    }
    __syncthreads();
}

// ---------------------------------------------------------------------------
// Persistent CSR build: count -> chunk scan (shfl) -> prefix -> fill
// Requires g_deg == 0 on entry; restores that invariant for the next call.
// ---------------------------------------------------------------------------
__global__ __launch_bounds__(1024) void build_kernel(
    const int* __restrict__ src, const int* __restrict__ tgt, int n, int E) {
    __shared__ int sh_w[32];
    __shared__ int sh_total;
    __shared__ int sh_coff;

    int t = threadIdx.x;
    int lane = t & 31;
    int warp = t >> 5;
    int bid = blockIdx.x;

    // Phase 1: count in-degrees
    for (int e = bid * 1024 + t; e < E; e += NBLK * 1024)
        atomicAdd(&g_deg[__ldg(&tgt[e])], 1);

    grid_bar();

    // Phase 2: per-chunk exclusive scan via warp shuffles; re-zero g_deg
    int chunk = (n + NBLK - 1) / NBLK;              // <= 1024
    int base = bid * chunk;
    int m = n - base; if (m > chunk) m = chunk; if (m < 0) m = 0;

    int v = 0;
    if (t < m) {
        v = __ldcg(&g_deg[base + t]);
        g_deg[base + t] = 0;
    }
    // warp inclusive scan
    int val = v;
#pragma unroll
    for (int s = 1; s < 32; s <<= 1) {
        int u = __shfl_up_sync(0xffffffffu, val, s);
        if (lane >= s) val += u;
    }
    if (lane == 31) sh_w[warp] = val;
    __syncthreads();
    if (warp == 0) {
        int wv = sh_w[lane];
        int wi = wv;
#pragma unroll
        for (int s = 1; s < 32; s <<= 1) {
            int u = __shfl_up_sync(0xffffffffu, wi, s);
            if (lane >= s) wi += u;
        }
        sh_w[lane] = wi - wv;                        // exclusive warp offset
        if (lane == 31) sh_total = wi;
    }
    __syncthreads();
    int excl = (val - v) + sh_w[warp];
    if (t < m) g_off[base + t] = excl;
    if (t == 0) g_csum[bid] = sh_total;

    grid_bar();

    // Phase 3: each block sums csum[0..bid) (warp 0), offsets own chunk
    if (warp == 0) {
        int p = 0;
        for (int i = lane; i < bid; i += 32) p += __ldcg(&g_csum[i]);
#pragma unroll
        for (int s = 16; s > 0; s >>= 1) p += __shfl_down_sync(0xffffffffu, p, s);
        if (lane == 0) sh_coff = p;
    }
    __syncthreads();
    int coff = sh_coff;
    if (t < m) {
        int o = g_off[base + t] + coff;
        g_off[base + t] = o;
        g_cur[base + t] = o;
    }

    grid_bar();

    // Phase 4: fill edge list via atomic cursors
    for (int e = bid * 1024 + t; e < E; e += NBLK * 1024) {
        int d = __ldg(&tgt[e]);
        int s = __ldg(&src[e]);
        int p = atomicAdd(&g_cur[d], 1);
        g_elist[p] = s;
    }
}

// ---------------------------------------------------------------------------
// GEMM core: C = X @ W^T (+b later). 128x64 tile, 256 threads, 32 FMA/thread/k.
// ---------------------------------------------------------------------------
#define SX_STRIDE 132
#define GEMM_SMEM_FLOATS (64 * SX_STRIDE + 64 * 68 + 64)

__device__ __forceinline__ void gemm_core(
    const float* __restrict__ X, const float* __restrict__ W,
    const float* __restrict__ b, int n, int row0,
    float* s_x, float* s_w, float* s_b, float accA[4][4], float accB[4][4]) {
    int t = threadIdx.x;
    for (int i = t; i < 128 * 64; i += 256) {
        int r = i >> 6, k = i & 63;
        int gr = row0 + r;
        s_x[k * SX_STRIDE + r] = (gr < n) ? X[gr * 64 + k] : 0.f;
    }
    for (int i = t; i < 64 * 64; i += 256) {
        int c = i >> 6, k = i & 63;
        s_w[k * 68 + c] = W[c * 64 + k];
    }
    if (t < 64) s_b[t] = b[t];
    __syncthreads();

    int tx = t & 15, ty = t >> 4;
#pragma unroll
    for (int i = 0; i < 4; i++)
#pragma unroll
        for (int j = 0; j < 4; j++) { accA[i][j] = 0.f; accB[i][j] = 0.f; }

#pragma unroll 8
    for (int k = 0; k < 64; k++) {
        float4 xa = *reinterpret_cast<const float4*>(&s_x[k * SX_STRIDE + ty * 4]);
        float4 xb = *reinterpret_cast<const float4*>(&s_x[k * SX_STRIDE + 64 + ty * 4]);
        float4 wv = *reinterpret_cast<const float4*>(&s_w[k * 68 + tx * 4]);
        float xsA[4] = {xa.x, xa.y, xa.z, xa.w};
        float xsB[4] = {xb.x, xb.y, xb.z, xb.w};
        float ws[4]  = {wv.x, wv.y, wv.z, wv.w};
#pragma unroll
        for (int i = 0; i < 4; i++)
#pragma unroll
            for (int j = 0; j < 4; j++) {
                accA[i][j] = fmaf(xsA[i], ws[j], accA[i][j]);
                accB[i][j] = fmaf(xsB[i], ws[j], accB[i][j]);
            }
    }
}

// ---------------------------------------------------------------------------
// GEMM 1: g_lin = data @ W_lin^T + b_lin  (+ fp16 shadow)
// ---------------------------------------------------------------------------
__global__ __launch_bounds__(256) void gemm_lin_kernel(
    const float* __restrict__ X, const float* __restrict__ W,
    const float* __restrict__ b, int n) {
    extern __shared__ float smem[];
    float* s_x = smem;
    float* s_w = smem + 64 * SX_STRIDE;
    float* s_b = s_w + 64 * 68;
    int row0 = blockIdx.x * 128;
    float accA[4][4], accB[4][4];
    gemm_core(X, W, b, n, row0, s_x, s_w, s_b, accA, accB);

    int t = threadIdx.x, tx = t & 15, ty = t >> 4;
#pragma unroll
    for (int half = 0; half < 2; half++) {
#pragma unroll
        for (int i = 0; i < 4; i++) {
            int gr = row0 + half * 64 + ty * 4 + i;
            if (gr < n) {
                float v0 = (half ? accB : accA)[i][0] + s_b[tx * 4 + 0];
                float v1 = (half ? accB : accA)[i][1] + s_b[tx * 4 + 1];
                float v2 = (half ? accB : accA)[i][2] + s_b[tx * 4 + 2];
                float v3 = (half ? accB : accA)[i][3] + s_b[tx * 4 + 3];
                *reinterpret_cast<float4*>(g_lin + gr * 64 + tx * 4) =
                    make_float4(v0, v1, v2, v3);
                g_lin_h[gr * 32 + tx * 2]     = __floats2half2_rn(v0, v1);
                g_lin_h[gr * 32 + tx * 2 + 1] = __floats2half2_rn(v2, v3);
            }
        }
    }
}

// ---------------------------------------------------------------------------
// Fused final: GEMM(merge) -> in-smem gather of lap for own 128 nodes ->
//              out = relu(gemm + b + lap).  s_lap reuses the dead s_x region.
// ---------------------------------------------------------------------------
__global__ __launch_bounds__(256) void final_fused_kernel(
    const float* __restrict__ M, const float* __restrict__ W,
    const float* __restrict__ b, float* __restrict__ out, int n, int E) {
    extern __shared__ float smem[];
    float* s_x = smem;
    float* s_w = smem + 64 * SX_STRIDE;
    float* s_b = s_w + 64 * 68;
    float* s_lap = smem;                  // union with s_x (dead after k-loop)

    int row0 = blockIdx.x * 128;
    float accA[4][4], accB[4][4];
    gemm_core(M, W, b, n, row0, s_x, s_w, s_b, accA, accB);

    __syncthreads();                      // everyone done reading s_x

    // Gather: warp per node, 16 nodes per warp
    int lane = threadIdx.x & 31;
    int warp = threadIdx.x >> 5;
    for (int i = warp; i < 128; i += 8) {
        int node = row0 + i;
        if (node >= n) break;
        int beg = g_off[node];
        int end = (node + 1 < n) ? g_off[node + 1] : E;

        float sx = 0.f, sy = 0.f;
        int j = beg;
        for (; j + 4 <= end; j += 4) {
            int s0 = g_elist[j];
            int s1 = g_elist[j + 1];
            int s2 = g_elist[j + 2];
            int s3 = g_elist[j + 3];
            float2 v0 = __half22float2(g_lin_h[s0 * 32 + lane]);
            float2 v1 = __half22float2(g_lin_h[s1 * 32 + lane]);
            float2 v2 = __half22float2(g_lin_h[s2 * 32 + lane]);
            float2 v3 = __half22float2(g_lin_h[s3 * 32 + lane]);
            sx += (v0.x + v1.x) + (v2.x + v3.x);
            sy += (v0.y + v1.y) + (v2.y + v3.y);
        }
        for (; j < end; j++) {
            float2 v = __half22float2(g_lin_h[g_elist[j] * 32 + lane]);
            sx += v.x;
            sy += v.y;
        }

        int deg = end - beg;
        float2 lv2;
        if (deg > 0) {
            float inv = 1.f / (float)deg;
            float2 lv = *reinterpret_cast<const float2*>(g_lin + node * 64 + lane * 2);
            lv2.x = lv.x - sx * inv;
            lv2.y = lv.y - sy * inv;
        } else {
            lv2 = make_float2(0.f, 0.f);
        }
        *reinterpret_cast<float2*>(&s_lap[i * 64 + lane * 2]) = lv2;
    }
    __syncthreads();

    // Epilogue: out = relu(acc + b + lap)
    int t = threadIdx.x, tx = t & 15, ty = t >> 4;
#pragma unroll
    for (int half = 0; half < 2; half++) {
#pragma unroll
        for (int i = 0; i < 4; i++) {
            int r = half * 64 + ty * 4 + i;
            int gr = row0 + r;
            if (gr < n) {
                float4 lp = *reinterpret_cast<const float4*>(&s_lap[r * 64 + tx * 4]);
                float v0 = (half ? accB : accA)[i][0] + s_b[tx * 4 + 0] + lp.x;
                float v1 = (half ? accB : accA)[i][1] + s_b[tx * 4 + 1] + lp.y;
                float v2 = (half ? accB : accA)[i][2] + s_b[tx * 4 + 2] + lp.z;
                float v3 = (half ? accB : accA)[i][3] + s_b[tx * 4 + 3] + lp.w;
                *reinterpret_cast<float4*>(out + gr * 64 + tx * 4) =
                    make_float4(fmaxf(v0, 0.f), fmaxf(v1, 0.f),
                                fmaxf(v2, 0.f), fmaxf(v3, 0.f));
            }
        }
    }
}

// ---------------------------------------------------------------------------
// Launch: 3 kernels.
// Inputs: data[N*64], merge[N*64], src_idx[E], tgt_idx[E],
//         W_lin[64*64], b_lin[64], W_tr[64*64], b_tr[64].  Output: float[N*64]
// ---------------------------------------------------------------------------
extern "C" void kernel_launch(void* const* d_in, const int* in_sizes, int n_in,
                              void* d_out, int out_size) {
    const float* data  = (const float*)d_in[0];
    const float* merge = (const float*)d_in[1];
    const int*   src   = (const int*)d_in[2];
    const int*   tgt   = (const int*)d_in[3];
    const float* W_lin = (const float*)d_in[4];
    const float* b_lin = (const float*)d_in[5];
    const float* W_tr  = (const float*)d_in[6];
    const float* b_tr  = (const float*)d_in[7];
    float* out = (float*)d_out;

    int n = in_sizes[0] / D;      // 50000
    int E = in_sizes[2];          // 800000

    size_t gemm_smem = GEMM_SMEM_FLOATS * sizeof(float);   // ~51.5 KB
    cudaFuncSetAttribute(gemm_lin_kernel,
                         cudaFuncAttributeMaxDynamicSharedMemorySize, (int)gemm_smem);
    cudaFuncSetAttribute(final_fused_kernel,
                         cudaFuncAttributeMaxDynamicSharedMemorySize, (int)gemm_smem);

    int gemm_blocks = (n + 127) / 128;

    build_kernel<<<NBLK, 1024>>>(src, tgt, n, E);
    gemm_lin_kernel<<<gemm_blocks, 256, gemm_smem>>>(data, W_lin, b_lin, n);
    final_fused_kernel<<<gemm_blocks, 256, gemm_smem>>>(merge, W_tr, b_tr, out, n, E);
}

// round 11
// speedup vs baseline: 1.0563x; 1.0563x over previous
#include <cuda_runtime.h>
#include <cuda_fp16.h>

#define MAX_NODES 50000
#define MAX_EDGES 800000
#define D 64

// ---------------------------------------------------------------------------
// Scratch (device globals; zero-initialized at load — g_deg invariant relies on it)
// ---------------------------------------------------------------------------
__device__ float   g_lin[MAX_NODES * D];       // data @ W_lin^T + b_lin (fp32)
__device__ __half2 g_lin_h[MAX_NODES * (D/2)]; // fp16 shadow for gather reads
__device__ float   g_lap[MAX_NODES * D];       // lin - (sum_src lin)/deg
__device__ int     g_deg[MAX_NODES];           // in-degree (zeroed by scanA each call)
__device__ int     g_off[MAX_NODES];           // CSR row offsets
__device__ int     g_cur[MAX_NODES];           // fill cursors
__device__ int     g_csum[64];                 // per-chunk sums (<= 49 chunks)
__device__ int     g_elist[MAX_EDGES];         // src ids in CSR order

// ---------------------------------------------------------------------------
// 1) count in-degrees
// ---------------------------------------------------------------------------
__global__ void count_kernel(const int* __restrict__ tgt, int E) {
    int i = blockIdx.x * blockDim.x + threadIdx.x;
    int e = i * 4;
    if (e + 4 <= E) {
        int4 t4 = *reinterpret_cast<const int4*>(tgt + e);
        atomicAdd(&g_deg[t4.x], 1);
        atomicAdd(&g_deg[t4.y], 1);
        atomicAdd(&g_deg[t4.z], 1);
        atomicAdd(&g_deg[t4.w], 1);
    } else {
        for (; e < E; e++) atomicAdd(&g_deg[tgt[e]], 1);
    }
}

// ---------------------------------------------------------------------------
// 2) per-chunk exclusive scan (warp shuffles), zero g_deg, emit chunk sum
//    (single writer for g_csum: thread 0, after the barrier)
// ---------------------------------------------------------------------------
__global__ __launch_bounds__(1024) void scanA_kernel(int n) {
    __shared__ int sh_w[32];
    __shared__ int sh_total;
    int t = threadIdx.x, lane = t & 31, warp = t >> 5;
    int gid = blockIdx.x * 1024 + t;

    int v = 0;
    if (gid < n) {
        v = g_deg[gid];
        g_deg[gid] = 0;                 // restore invariant for next call
    }
    int val = v;
#pragma unroll
    for (int s = 1; s < 32; s <<= 1) {
        int u = __shfl_up_sync(0xffffffffu, val, s);
        if (lane >= s) val += u;
    }
    if (lane == 31) sh_w[warp] = val;
    __syncthreads();
    if (warp == 0) {
        int wv = sh_w[lane];
        int wi = wv;
#pragma unroll
        for (int s = 1; s < 32; s <<= 1) {
            int u = __shfl_up_sync(0xffffffffu, wi, s);
            if (lane >= s) wi += u;
        }
        sh_w[lane] = wi - wv;           // exclusive warp offset
        if (lane == 31) sh_total = wi;  // chunk total
    }
    __syncthreads();
    if (gid < n) g_off[gid] = (val - v) + sh_w[warp];
    if (t == 0) g_csum[blockIdx.x] = sh_total;   // SINGLE writer
}

// ---------------------------------------------------------------------------
// 3) add chunk prefix (redundant per-block 64-wide scan), init cursors
// ---------------------------------------------------------------------------
__global__ __launch_bounds__(256) void scanBC_kernel(int n, int nchunk) {
    __shared__ int sh[64];
    int t = threadIdx.x;
    if (t < 64) sh[t] = (t < nchunk) ? g_csum[t] : 0;
    __syncthreads();
#pragma unroll
    for (int s = 1; s < 64; s <<= 1) {
        int a = (t >= s && t < 64) ? sh[t - s] : 0;
        __syncthreads();
        if (t < 64) sh[t] += a;
        __syncthreads();
    }
    int i = blockIdx.x * 256 + t;
    if (i < n) {
        int c = i >> 10;
        int coff = (c > 0) ? sh[c - 1] : 0;
        int o = g_off[i] + coff;
        g_off[i] = o;
        g_cur[i] = o;
    }
}

// ---------------------------------------------------------------------------
// 4) fill CSR edge list via atomic cursors
// ---------------------------------------------------------------------------
__global__ void fill_kernel(const int* __restrict__ src,
                            const int* __restrict__ tgt, int E) {
    int e = blockIdx.x * blockDim.x + threadIdx.x;
    if (e < E) {
        int p = atomicAdd(&g_cur[tgt[e]], 1);
        g_elist[p] = src[e];
    }
}

// ---------------------------------------------------------------------------
// GEMM core: 256x64 block tile, 256 threads, 8x8 register tile per thread.
// Per thread-k: 4 LDS.128 feed 64 FMA -> FFMA-bound.
// ---------------------------------------------------------------------------
#define SXS 260
#define GEMM_SMEM_FLOATS (64 * SXS + 64 * 68 + 64)   // ~84.2 KB

__device__ __forceinline__ void gemm_core8(
    const float* __restrict__ X, const float* __restrict__ W,
    const float* __restrict__ b, int n, int row0,
    float* s_x, float* s_w, float* s_b, float acc[8][8]) {
    int t = threadIdx.x;
    for (int i = t; i < 256 * 64; i += 256) {
        int r = i >> 6, k = i & 63;
        int gr = row0 + r;
        s_x[k * SXS + r] = (gr < n) ? X[gr * 64 + k] : 0.f;
    }
    for (int i = t; i < 64 * 64; i += 256) {
        int c = i >> 6, k = i & 63;
        s_w[k * 68 + c] = W[c * 64 + k];
    }
    if (t < 64) s_b[t] = b[t];
    __syncthreads();

    int tx = t & 7, ty = t >> 3;
#pragma unroll
    for (int i = 0; i < 8; i++)
#pragma unroll
        for (int j = 0; j < 8; j++) acc[i][j] = 0.f;

#pragma unroll 4
    for (int k = 0; k < 64; k++) {
        float4 xa = *reinterpret_cast<const float4*>(&s_x[k * SXS + ty * 8]);
        float4 xb = *reinterpret_cast<const float4*>(&s_x[k * SXS + ty * 8 + 4]);
        float4 wa = *reinterpret_cast<const float4*>(&s_w[k * 68 + tx * 8]);
        float4 wb = *reinterpret_cast<const float4*>(&s_w[k * 68 + tx * 8 + 4]);
        float xs[8] = {xa.x, xa.y, xa.z, xa.w, xb.x, xb.y, xb.z, xb.w};
        float ws[8] = {wa.x, wa.y, wa.z, wa.w, wb.x, wb.y, wb.z, wb.w};
#pragma unroll
        for (int i = 0; i < 8; i++)
#pragma unroll
            for (int j = 0; j < 8; j++) acc[i][j] = fmaf(xs[i], ws[j], acc[i][j]);
    }
}

// ---------------------------------------------------------------------------
// 5) GEMM 1: g_lin = data @ W_lin^T + b_lin  (+ packed fp16 shadow)
// ---------------------------------------------------------------------------
__global__ __launch_bounds__(256) void gemm_lin_kernel(
    const float* __restrict__ X, const float* __restrict__ W,
    const float* __restrict__ b, int n) {
    extern __shared__ float smem[];
    float* s_x = smem;
    float* s_w = smem + 64 * SXS;
    float* s_b = s_w + 64 * 68;
    int row0 = blockIdx.x * 256;
    float acc[8][8];
    gemm_core8(X, W, b, n, row0, s_x, s_w, s_b, acc);

    int t = threadIdx.x, tx = t & 7, ty = t >> 3;
    float bj[8];
#pragma unroll
    for (int j = 0; j < 8; j++) bj[j] = s_b[tx * 8 + j];

#pragma unroll
    for (int i = 0; i < 8; i++) {
        int gr = row0 + ty * 8 + i;
        if (gr < n) {
            float v[8];
#pragma unroll
            for (int j = 0; j < 8; j++) v[j] = acc[i][j] + bj[j];
            float* gp = g_lin + gr * 64 + tx * 8;
            *reinterpret_cast<float4*>(gp)     = make_float4(v[0], v[1], v[2], v[3]);
            *reinterpret_cast<float4*>(gp + 4) = make_float4(v[4], v[5], v[6], v[7]);
            __half2 h[4];
#pragma unroll
            for (int j = 0; j < 4; j++) h[j] = __floats2half2_rn(v[2*j], v[2*j+1]);
            *reinterpret_cast<float4*>(&g_lin_h[gr * 32 + tx * 4]) =
                *reinterpret_cast<const float4*>(h);
        }
    }
}

// ---------------------------------------------------------------------------
// 6) gather: warp per node, fp16 reads, fp32 accumulate
// ---------------------------------------------------------------------------
__global__ __launch_bounds__(256) void gather_kernel(int n, int E) {
    int w = (blockIdx.x * 256 + threadIdx.x) >> 5;
    int lane = threadIdx.x & 31;
    if (w >= n) return;

    int beg = g_off[w];
    int end = (w + 1 < n) ? g_off[w + 1] : E;

    float sx = 0.f, sy = 0.f;
    int j = beg;
    for (; j + 4 <= end; j += 4) {
        int s0 = g_elist[j];
        int s1 = g_elist[j + 1];
        int s2 = g_elist[j + 2];
        int s3 = g_elist[j + 3];
        float2 v0 = __half22float2(g_lin_h[s0 * 32 + lane]);
        float2 v1 = __half22float2(g_lin_h[s1 * 32 + lane]);
        float2 v2 = __half22float2(g_lin_h[s2 * 32 + lane]);
        float2 v3 = __half22float2(g_lin_h[s3 * 32 + lane]);
        sx += (v0.x + v1.x) + (v2.x + v3.x);
        sy += (v0.y + v1.y) + (v2.y + v3.y);
    }
    for (; j < end; j++) {
        float2 v = __half22float2(g_lin_h[g_elist[j] * 32 + lane]);
        sx += v.x;
        sy += v.y;
    }

    int deg = end - beg;
    float2 outv;
    if (deg > 0) {
        float inv = 1.f / (float)deg;
        float2 lv = *reinterpret_cast<const float2*>(g_lin + w * 64 + lane * 2);
        outv.x = lv.x - sx * inv;
        outv.y = lv.y - sy * inv;
    } else {
        outv = make_float2(0.f, 0.f);
    }
    reinterpret_cast<float2*>(g_lap + w * 64)[lane] = outv;
}

// ---------------------------------------------------------------------------
// 7) final: out = relu( merge @ W_tr^T + b_tr + lap )
// ---------------------------------------------------------------------------
__global__ __launch_bounds__(256) void final_kernel(
    const float* __restrict__ M, const float* __restrict__ W,
    const float* __restrict__ b, float* __restrict__ out, int n) {
    extern __shared__ float smem[];
    float* s_x = smem;
    float* s_w = smem + 64 * SXS;
    float* s_b = s_w + 64 * 68;
    int row0 = blockIdx.x * 256;
    float acc[8][8];
    gemm_core8(M, W, b, n, row0, s_x, s_w, s_b, acc);

    int t = threadIdx.x, tx = t & 7, ty = t >> 3;
    float bj[8];
#pragma unroll
    for (int j = 0; j < 8; j++) bj[j] = s_b[tx * 8 + j];

#pragma unroll
    for (int i = 0; i < 8; i++) {
        int gr = row0 + ty * 8 + i;
        if (gr < n) {
            const float* lp = g_lap + gr * 64 + tx * 8;
            float4 l0 = *reinterpret_cast<const float4*>(lp);
            float4 l1 = *reinterpret_cast<const float4*>(lp + 4);
            float la[8] = {l0.x, l0.y, l0.z, l0.w, l1.x, l1.y, l1.z, l1.w};
            float v[8];
#pragma unroll
            for (int j = 0; j < 8; j++) v[j] = fmaxf(acc[i][j] + bj[j] + la[j], 0.f);
            float* op = out + gr * 64 + tx * 8;
            *reinterpret_cast<float4*>(op)     = make_float4(v[0], v[1], v[2], v[3]);
            *reinterpret_cast<float4*>(op + 4) = make_float4(v[4], v[5], v[6], v[7]);
        }
    }
}

// ---------------------------------------------------------------------------
// Launch: 7 kernels.
// Inputs: data[N*64], merge[N*64], src_idx[E], tgt_idx[E],
//         W_lin[64*64], b_lin[64], W_tr[64*64], b_tr[64].  Output: float[N*64]
// ---------------------------------------------------------------------------
extern "C" void kernel_launch(void* const* d_in, const int* in_sizes, int n_in,
                              void* d_out, int out_size) {
    const float* data  = (const float*)d_in[0];
    const float* merge = (const float*)d_in[1];
    const int*   src   = (const int*)d_in[2];
    const int*   tgt   = (const int*)d_in[3];
    const float* W_lin = (const float*)d_in[4];
    const float* b_lin = (const float*)d_in[5];
    const float* W_tr  = (const float*)d_in[6];
    const float* b_tr  = (const float*)d_in[7];
    float* out = (float*)d_out;

    int n = in_sizes[0] / D;      // 50000
    int E = in_sizes[2];          // 800000
    int nchunk = (n + 1023) >> 10;

    size_t gemm_smem = GEMM_SMEM_FLOATS * sizeof(float);
    cudaFuncSetAttribute(gemm_lin_kernel,
                         cudaFuncAttributeMaxDynamicSharedMemorySize, (int)gemm_smem);
    cudaFuncSetAttribute(final_kernel,
                         cudaFuncAttributeMaxDynamicSharedMemorySize, (int)gemm_smem);

    int gemm_blocks = (n + 255) / 256;

    count_kernel<<<((E + 3) / 4 + 255) / 256, 256>>>(tgt, E);
    scanA_kernel<<<nchunk, 1024>>>(n);
    scanBC_kernel<<<(n + 255) / 256, 256>>>(n, nchunk);
    fill_kernel<<<(E + 255) / 256, 256>>>(src, tgt, E);
    gemm_lin_kernel<<<gemm_blocks, 256, gemm_smem>>>(data, W_lin, b_lin, n);
    gather_kernel<<<(n * 32 + 255) / 256, 256>>>(n, E);
    final_kernel<<<gemm_blocks, 256, gemm_smem>>>(merge, W_tr, b_tr, out, n);
}

// round 13
// speedup vs baseline: 1.3255x; 1.2549x over previous
#include <cuda_runtime.h>
#include <cuda_fp16.h>

#define MAX_NODES 50000
#define MAX_EDGES 800000
#define D 64

// ---------------------------------------------------------------------------
// Scratch (device globals; zero-initialized at load — g_deg invariant relies on it)
// ---------------------------------------------------------------------------
__device__ float   g_lin[MAX_NODES * D];       // data @ W_lin^T + b_lin (fp32)
__device__ __half2 g_lin_h[MAX_NODES * (D/2)]; // fp16 shadow for gather reads
__device__ float   g_lap[MAX_NODES * D];       // lin - (sum_src lin)/deg
__device__ int     g_deg[MAX_NODES];           // in-degree (zeroed by scanA each call)
__device__ int     g_off[MAX_NODES];           // CSR row offsets
__device__ int     g_cur[MAX_NODES];           // fill cursors
__device__ int     g_csum[64];                 // per-chunk sums (<= 49 chunks)
__device__ int     g_elist[MAX_EDGES];         // src ids in CSR order

// ---------------------------------------------------------------------------
// 1) count in-degrees
// ---------------------------------------------------------------------------
__global__ void count_kernel(const int* __restrict__ tgt, int E) {
    int i = blockIdx.x * blockDim.x + threadIdx.x;
    int e = i * 4;
    if (e + 4 <= E) {
        int4 t4 = *reinterpret_cast<const int4*>(tgt + e);
        atomicAdd(&g_deg[t4.x], 1);
        atomicAdd(&g_deg[t4.y], 1);
        atomicAdd(&g_deg[t4.z], 1);
        atomicAdd(&g_deg[t4.w], 1);
    } else {
        for (; e < E; e++) atomicAdd(&g_deg[tgt[e]], 1);
    }
}

// ---------------------------------------------------------------------------
// 2) per-chunk exclusive scan (warp shuffles), zero g_deg, emit chunk sum
// ---------------------------------------------------------------------------
__global__ __launch_bounds__(1024) void scanA_kernel(int n) {
    __shared__ int sh_w[32];
    __shared__ int sh_total;
    int t = threadIdx.x, lane = t & 31, warp = t >> 5;
    int gid = blockIdx.x * 1024 + t;

    int v = 0;
    if (gid < n) {
        v = g_deg[gid];
        g_deg[gid] = 0;
    }
    int val = v;
#pragma unroll
    for (int s = 1; s < 32; s <<= 1) {
        int u = __shfl_up_sync(0xffffffffu, val, s);
        if (lane >= s) val += u;
    }
    if (lane == 31) sh_w[warp] = val;
    __syncthreads();
    if (warp == 0) {
        int wv = sh_w[lane];
        int wi = wv;
#pragma unroll
        for (int s = 1; s < 32; s <<= 1) {
            int u = __shfl_up_sync(0xffffffffu, wi, s);
            if (lane >= s) wi += u;
        }
        sh_w[lane] = wi - wv;
        if (lane == 31) sh_total = wi;
    }
    __syncthreads();
    if (gid < n) g_off[gid] = (val - v) + sh_w[warp];
    if (t == 0) g_csum[blockIdx.x] = sh_total;   // single writer
}

// ---------------------------------------------------------------------------
// 3) add chunk prefix (redundant per-block 64-wide scan), init cursors
// ---------------------------------------------------------------------------
__global__ __launch_bounds__(256) void scanBC_kernel(int n, int nchunk) {
    __shared__ int sh[64];
    int t = threadIdx.x;
    if (t < 64) sh[t] = (t < nchunk) ? g_csum[t] : 0;
    __syncthreads();
#pragma unroll
    for (int s = 1; s < 64; s <<= 1) {
        int a = (t >= s && t < 64) ? sh[t - s] : 0;
        __syncthreads();
        if (t < 64) sh[t] += a;
        __syncthreads();
    }
    int i = blockIdx.x * 256 + t;
    if (i < n) {
        int c = i >> 10;
        int coff = (c > 0) ? sh[c - 1] : 0;
        int o = g_off[i] + coff;
        g_off[i] = o;
        g_cur[i] = o;
    }
}

// ---------------------------------------------------------------------------
// 4) fill CSR edge list via atomic cursors
// ---------------------------------------------------------------------------
__global__ void fill_kernel(const int* __restrict__ src,
                            const int* __restrict__ tgt, int E) {
    int e = blockIdx.x * blockDim.x + threadIdx.x;
    if (e < E) {
        int p = atomicAdd(&g_cur[tgt[e]], 1);
        g_elist[p] = src[e];
    }
}

// ---------------------------------------------------------------------------
// tf32 tensor-core GEMM: OUT[128x64] = X[128x64] @ W[64x64]^T  per block.
// 8 warps; warp w computes rows [w*16, w*16+16) x all 64 cols.
// Per warp: 8 k-steps x 8 n-tiles of mma.m16n8k8 (A row-major, B col-major=W rows).
// smem holds tf32-converted bit patterns; fragment LDS are conflict-free.
// ---------------------------------------------------------------------------
#define XS 68
#define GEMM_SMEM_FLOATS (128 * XS + 64 * XS + 64)   // ~52.5 KB

__device__ __forceinline__ unsigned f2tf32(float f) {
    unsigned u;
    asm("cvt.rna.tf32.f32 %0, %1;" : "=r"(u) : "f"(f));
    return u;
}

__device__ __forceinline__ void mma_tf32(float c[4], const unsigned a[4],
                                         const unsigned b[2]) {
    asm volatile(
        "mma.sync.aligned.m16n8k8.row.col.f32.tf32.tf32.f32 "
        "{%0,%1,%2,%3}, {%4,%5,%6,%7}, {%8,%9}, {%0,%1,%2,%3};"
        : "+f"(c[0]), "+f"(c[1]), "+f"(c[2]), "+f"(c[3])
        : "r"(a[0]), "r"(a[1]), "r"(a[2]), "r"(a[3]), "r"(b[0]), "r"(b[1]));
}

// Core: fills acc[nt][4] for this thread. s_x/s_w hold tf32 bits as uint.
__device__ __forceinline__ void gemm_core_tc(
    const float* __restrict__ X, const float* __restrict__ W,
    const float* __restrict__ b, int n, int row0,
    unsigned* s_x, unsigned* s_w, float* s_b, float acc[8][4]) {
    int t = threadIdx.x;
    for (int i = t; i < 128 * 64; i += 256) {
        int r = i >> 6, k = i & 63;
        int gr = row0 + r;
        s_x[r * XS + k] = (gr < n) ? f2tf32(X[gr * 64 + k]) : 0u;
    }
    for (int i = t; i < 64 * 64; i += 256) {
        int c = i >> 6, k = i & 63;
        s_w[c * XS + k] = f2tf32(W[c * 64 + k]);
    }
    if (t < 64) s_b[t] = b[t];
    __syncthreads();

    int lane = t & 31, warp = t >> 5;
    int g = lane >> 2, tg = lane & 3;         // groupID, threadID-in-group
    int m0 = warp * 16;

#pragma unroll
    for (int nt = 0; nt < 8; nt++)
#pragma unroll
        for (int j = 0; j < 4; j++) acc[nt][j] = 0.f;

#pragma unroll
    for (int ks = 0; ks < 8; ks++) {
        int k0 = ks * 8;
        unsigned a[4];
        a[0] = s_x[(m0 + g) * XS + k0 + tg];
        a[1] = s_x[(m0 + g + 8) * XS + k0 + tg];
        a[2] = s_x[(m0 + g) * XS + k0 + tg + 4];
        a[3] = s_x[(m0 + g + 8) * XS + k0 + tg + 4];
#pragma unroll
        for (int nt = 0; nt < 8; nt++) {
            unsigned bb[2];
            int nn = nt * 8 + g;
            bb[0] = s_w[nn * XS + k0 + tg];
            bb[1] = s_w[nn * XS + k0 + tg + 4];
            mma_tf32(acc[nt], a, bb);
        }
    }
}

// ---------------------------------------------------------------------------
// 5) GEMM 1: g_lin = data @ W_lin^T + b_lin  (+ packed fp16 shadow)
// ---------------------------------------------------------------------------
__global__ __launch_bounds__(256) void gemm_lin_kernel(
    const float* __restrict__ X, const float* __restrict__ W,
    const float* __restrict__ b, int n) {
    extern __shared__ float smem[];
    unsigned* s_x = reinterpret_cast<unsigned*>(smem);
    unsigned* s_w = reinterpret_cast<unsigned*>(smem + 128 * XS);
    float* s_b = smem + 128 * XS + 64 * XS;
    int row0 = blockIdx.x * 128;
    float acc[8][4];
    gemm_core_tc(X, W, b, n, row0, s_x, s_w, s_b, acc);

    int lane = threadIdx.x & 31, warp = threadIdx.x >> 5;
    int g = lane >> 2, tg = lane & 3;
    int m0 = warp * 16;

#pragma unroll
    for (int half = 0; half < 2; half++) {
        int gr = row0 + m0 + g + half * 8;
        if (gr < n) {
#pragma unroll
            for (int nt = 0; nt < 8; nt++) {
                int c = nt * 8 + 2 * tg;
                float v0 = acc[nt][half * 2 + 0] + s_b[c];
                float v1 = acc[nt][half * 2 + 1] + s_b[c + 1];
                *reinterpret_cast<float2*>(g_lin + gr * 64 + c) =
                    make_float2(v0, v1);
                g_lin_h[gr * 32 + (c >> 1)] = __floats2half2_rn(v0, v1);
            }
        }
    }
}

// ---------------------------------------------------------------------------
// 6) gather: warp per node, fp16 reads, fp32 accumulate
// ---------------------------------------------------------------------------
__global__ __launch_bounds__(256) void gather_kernel(int n, int E) {
    int w = (blockIdx.x * 256 + threadIdx.x) >> 5;
    int lane = threadIdx.x & 31;
    if (w >= n) return;

    int beg = g_off[w];
    int end = (w + 1 < n) ? g_off[w + 1] : E;

    float sx = 0.f, sy = 0.f;
    int j = beg;
    for (; j + 4 <= end; j += 4) {
        int s0 = g_elist[j];
        int s1 = g_elist[j + 1];
        int s2 = g_elist[j + 2];
        int s3 = g_elist[j + 3];
        float2 v0 = __half22float2(g_lin_h[s0 * 32 + lane]);
        float2 v1 = __half22float2(g_lin_h[s1 * 32 + lane]);
        float2 v2 = __half22float2(g_lin_h[s2 * 32 + lane]);
        float2 v3 = __half22float2(g_lin_h[s3 * 32 + lane]);
        sx += (v0.x + v1.x) + (v2.x + v3.x);
        sy += (v0.y + v1.y) + (v2.y + v3.y);
    }
    for (; j < end; j++) {
        float2 v = __half22float2(g_lin_h[g_elist[j] * 32 + lane]);
        sx += v.x;
        sy += v.y;
    }

    int deg = end - beg;
    float2 outv;
    if (deg > 0) {
        float inv = 1.f / (float)deg;
        float2 lv = *reinterpret_cast<const float2*>(g_lin + w * 64 + lane * 2);
        outv.x = lv.x - sx * inv;
        outv.y = lv.y - sy * inv;
    } else {
        outv = make_float2(0.f, 0.f);
    }
    reinterpret_cast<float2*>(g_lap + w * 64)[lane] = outv;
}

// ---------------------------------------------------------------------------
// 7) final: out = relu( merge @ W_tr^T + b_tr + lap )
// ---------------------------------------------------------------------------
__global__ __launch_bounds__(256) void final_kernel(
    const float* __restrict__ M, const float* __restrict__ W,
    const float* __restrict__ b, float* __restrict__ out, int n) {
    extern __shared__ float smem[];
    unsigned* s_x = reinterpret_cast<unsigned*>(smem);
    unsigned* s_w = reinterpret_cast<unsigned*>(smem + 128 * XS);
    float* s_b = smem + 128 * XS + 64 * XS;
    int row0 = blockIdx.x * 128;
    float acc[8][4];
    gemm_core_tc(M, W, b, n, row0, s_x, s_w, s_b, acc);

    int lane = threadIdx.x & 31, warp = threadIdx.x >> 5;
    int g = lane >> 2, tg = lane & 3;
    int m0 = warp * 16;

#pragma unroll
    for (int half = 0; half < 2; half++) {
        int gr = row0 + m0 + g + half * 8;
        if (gr < n) {
#pragma unroll
            for (int nt = 0; nt < 8; nt++) {
                int c = nt * 8 + 2 * tg;
                float2 lp = *reinterpret_cast<const float2*>(g_lap + gr * 64 + c);
                float v0 = fmaxf(acc[nt][half * 2 + 0] + s_b[c] + lp.x, 0.f);
                float v1 = fmaxf(acc[nt][half * 2 + 1] + s_b[c + 1] + lp.y, 0.f);
                *reinterpret_cast<float2*>(out + gr * 64 + c) =
                    make_float2(v0, v1);
            }
        }
    }
}

// ---------------------------------------------------------------------------
// Launch: 7 kernels.
// Inputs: data[N*64], merge[N*64], src_idx[E], tgt_idx[E],
//         W_lin[64*64], b_lin[64], W_tr[64*64], b_tr[64].  Output: float[N*64]
// ---------------------------------------------------------------------------
extern "C" void kernel_launch(void* const* d_in, const int* in_sizes, int n_in,
                              void* d_out, int out_size) {
    const float* data  = (const float*)d_in[0];
    const float* merge = (const float*)d_in[1];
    const int*   src   = (const int*)d_in[2];
    const int*   tgt   = (const int*)d_in[3];
    const float* W_lin = (const float*)d_in[4];
    const float* b_lin = (const float*)d_in[5];
    const float* W_tr  = (const float*)d_in[6];
    const float* b_tr  = (const float*)d_in[7];
    float* out = (float*)d_out;

    int n = in_sizes[0] / D;      // 50000
    int E = in_sizes[2];          // 800000
    int nchunk = (n + 1023) >> 10;

    size_t gemm_smem = GEMM_SMEM_FLOATS * sizeof(float);   // ~52.5 KB
    cudaFuncSetAttribute(gemm_lin_kernel,
                         cudaFuncAttributeMaxDynamicSharedMemorySize, (int)gemm_smem);
    cudaFuncSetAttribute(final_kernel,
                         cudaFuncAttributeMaxDynamicSharedMemorySize, (int)gemm_smem);

    int gemm_blocks = (n + 127) / 128;

    count_kernel<<<((E + 3) / 4 + 255) / 256, 256>>>(tgt, E);
    scanA_kernel<<<nchunk, 1024>>>(n);
    scanBC_kernel<<<(n + 255) / 256, 256>>>(n, nchunk);
    fill_kernel<<<(E + 255) / 256, 256>>>(src, tgt, E);
    gemm_lin_kernel<<<gemm_blocks, 256, gemm_smem>>>(data, W_lin, b_lin, n);
    gather_kernel<<<(n * 32 + 255) / 256, 256>>>(n, E);
    final_kernel<<<gemm_blocks, 256, gemm_smem>>>(merge, W_tr, b_tr, out, n);
}

// round 16
// speedup vs baseline: 1.3589x; 1.0252x over previous
#include <cuda_runtime.h>
#include <cuda_fp16.h>

#define MAX_NODES 50000
#define MAX_EDGES 800000
#define D 64

// ---------------------------------------------------------------------------
// Scratch (device globals; zero-initialized at load — g_deg invariant relies on it)
// ---------------------------------------------------------------------------
__device__ float   g_lin[MAX_NODES * D];       // data @ W_lin^T + b_lin (fp32)
__device__ __half2 g_lin_h[MAX_NODES * (D/2)]; // fp16 shadow for gather reads
__device__ float   g_lap[MAX_NODES * D];       // lin - (sum_src lin)/deg
__device__ int     g_deg[MAX_NODES];           // in-degree (zeroed by scanA each call)
__device__ int     g_off[MAX_NODES];           // CSR row offsets
__device__ int     g_cur[MAX_NODES];           // fill cursors
__device__ int     g_csum[64];                 // per-chunk sums (<= 49 chunks)
__device__ int     g_elist[MAX_EDGES];         // src ids in CSR order

// ---------------------------------------------------------------------------
// 1) count in-degrees (RED, no return; 4 edges/thread)
// ---------------------------------------------------------------------------
__global__ void count_kernel(const int* __restrict__ tgt, int E) {
    int i = blockIdx.x * blockDim.x + threadIdx.x;
    int e = i * 4;
    if (e + 4 <= E) {
        int4 t4 = *reinterpret_cast<const int4*>(tgt + e);
        atomicAdd(&g_deg[t4.x], 1);
        atomicAdd(&g_deg[t4.y], 1);
        atomicAdd(&g_deg[t4.z], 1);
        atomicAdd(&g_deg[t4.w], 1);
    } else {
        for (; e < E; e++) atomicAdd(&g_deg[tgt[e]], 1);
    }
}

// ---------------------------------------------------------------------------
// 2) per-chunk exclusive scan (warp shuffles), zero g_deg, emit chunk sum
// ---------------------------------------------------------------------------
__global__ __launch_bounds__(1024) void scanA_kernel(int n) {
    __shared__ int sh_w[32];
    __shared__ int sh_total;
    int t = threadIdx.x, lane = t & 31, warp = t >> 5;
    int gid = blockIdx.x * 1024 + t;

    int v = 0;
    if (gid < n) {
        v = g_deg[gid];
        g_deg[gid] = 0;
    }
    int val = v;
#pragma unroll
    for (int s = 1; s < 32; s <<= 1) {
        int u = __shfl_up_sync(0xffffffffu, val, s);
        if (lane >= s) val += u;
    }
    if (lane == 31) sh_w[warp] = val;
    __syncthreads();
    if (warp == 0) {
        int wv = sh_w[lane];
        int wi = wv;
#pragma unroll
        for (int s = 1; s < 32; s <<= 1) {
            int u = __shfl_up_sync(0xffffffffu, wi, s);
            if (lane >= s) wi += u;
        }
        sh_w[lane] = wi - wv;
        if (lane == 31) sh_total = wi;
    }
    __syncthreads();
    if (gid < n) g_off[gid] = (val - v) + sh_w[warp];
    if (t == 0) g_csum[blockIdx.x] = sh_total;   // single writer
}

// ---------------------------------------------------------------------------
// 3) add chunk prefix (redundant per-block 64-wide scan), init cursors
// ---------------------------------------------------------------------------
__global__ __launch_bounds__(256) void scanBC_kernel(int n, int nchunk) {
    __shared__ int sh[64];
    int t = threadIdx.x;
    if (t < 64) sh[t] = (t < nchunk) ? g_csum[t] : 0;
    __syncthreads();
#pragma unroll
    for (int s = 1; s < 64; s <<= 1) {
        int a = (t >= s && t < 64) ? sh[t - s] : 0;
        __syncthreads();
        if (t < 64) sh[t] += a;
        __syncthreads();
    }
    int i = blockIdx.x * 256 + t;
    if (i < n) {
        int c = i >> 10;
        int coff = (c > 0) ? sh[c - 1] : 0;
        int o = g_off[i] + coff;
        g_off[i] = o;
        g_cur[i] = o;
    }
}

// ---------------------------------------------------------------------------
// 4) fill CSR edge list: 4 edges per thread -> 4 pipelined ATOMG (MLP=4)
// ---------------------------------------------------------------------------
__global__ void fill_kernel(const int* __restrict__ src,
                            const int* __restrict__ tgt, int E) {
    int i = blockIdx.x * blockDim.x + threadIdx.x;
    int e = i * 4;
    if (e + 4 <= E) {
        int4 t4 = *reinterpret_cast<const int4*>(tgt + e);
        int4 s4 = *reinterpret_cast<const int4*>(src + e);
        int p0 = atomicAdd(&g_cur[t4.x], 1);
        int p1 = atomicAdd(&g_cur[t4.y], 1);
        int p2 = atomicAdd(&g_cur[t4.z], 1);
        int p3 = atomicAdd(&g_cur[t4.w], 1);
        g_elist[p0] = s4.x;
        g_elist[p1] = s4.y;
        g_elist[p2] = s4.z;
        g_elist[p3] = s4.w;
    } else {
        for (; e < E; e++) {
            int p = atomicAdd(&g_cur[tgt[e]], 1);
            g_elist[p] = src[e];
        }
    }
}

// ---------------------------------------------------------------------------
// tf32 tensor-core GEMM: OUT[128x64] = X[128x64] @ W[64x64]^T  per block.
// 8 warps; warp w computes rows [w*16, w*16+16) x all 64 cols.
// ---------------------------------------------------------------------------
#define XS 68
#define GEMM_SMEM_FLOATS (128 * XS + 64 * XS + 64)   // ~52.5 KB

__device__ __forceinline__ unsigned f2tf32(float f) {
    unsigned u;
    asm("cvt.rna.tf32.f32 %0, %1;" : "=r"(u) : "f"(f));
    return u;
}

__device__ __forceinline__ void mma_tf32(float c[4], const unsigned a[4],
                                         const unsigned b[2]) {
    asm volatile(
        "mma.sync.aligned.m16n8k8.row.col.f32.tf32.tf32.f32 "
        "{%0,%1,%2,%3}, {%4,%5,%6,%7}, {%8,%9}, {%0,%1,%2,%3};"
        : "+f"(c[0]), "+f"(c[1]), "+f"(c[2]), "+f"(c[3])
        : "r"(a[0]), "r"(a[1]), "r"(a[2]), "r"(a[3]), "r"(b[0]), "r"(b[1]));
}

__device__ __forceinline__ void gemm_core_tc(
    const float* __restrict__ X, const float* __restrict__ W,
    const float* __restrict__ b, int n, int row0,
    unsigned* s_x, unsigned* s_w, float* s_b, float acc[8][4]) {
    int t = threadIdx.x;
    for (int i = t; i < 128 * 64; i += 256) {
        int r = i >> 6, k = i & 63;
        int gr = row0 + r;
        s_x[r * XS + k] = (gr < n) ? f2tf32(X[gr * 64 + k]) : 0u;
    }
    for (int i = t; i < 64 * 64; i += 256) {
        int c = i >> 6, k = i & 63;
        s_w[c * XS + k] = f2tf32(W[c * 64 + k]);
    }
    if (t < 64) s_b[t] = b[t];
    __syncthreads();

    int lane = t & 31, warp = t >> 5;
    int g = lane >> 2, tg = lane & 3;
    int m0 = warp * 16;

#pragma unroll
    for (int nt = 0; nt < 8; nt++)
#pragma unroll
        for (int j = 0; j < 4; j++) acc[nt][j] = 0.f;

#pragma unroll
    for (int ks = 0; ks < 8; ks++) {
        int k0 = ks * 8;
        unsigned a[4];
        a[0] = s_x[(m0 + g) * XS + k0 + tg];
        a[1] = s_x[(m0 + g + 8) * XS + k0 + tg];
        a[2] = s_x[(m0 + g) * XS + k0 + tg + 4];
        a[3] = s_x[(m0 + g + 8) * XS + k0 + tg + 4];
#pragma unroll
        for (int nt = 0; nt < 8; nt++) {
            unsigned bb[2];
            int nn = nt * 8 + g;
            bb[0] = s_w[nn * XS + k0 + tg];
            bb[1] = s_w[nn * XS + k0 + tg + 4];
            mma_tf32(acc[nt], a, bb);
        }
    }
}

// ---------------------------------------------------------------------------
// 5) GEMM 1: g_lin = data @ W_lin^T + b_lin  (+ packed fp16 shadow)
// ---------------------------------------------------------------------------
__global__ __launch_bounds__(256) void gemm_lin_kernel(
    const float* __restrict__ X, const float* __restrict__ W,
    const float* __restrict__ b, int n) {
    extern __shared__ float smem[];
    unsigned* s_x = reinterpret_cast<unsigned*>(smem);
    unsigned* s_w = reinterpret_cast<unsigned*>(smem + 128 * XS);
    float* s_b = smem + 128 * XS + 64 * XS;
    int row0 = blockIdx.x * 128;
    float acc[8][4];
    gemm_core_tc(X, W, b, n, row0, s_x, s_w, s_b, acc);

    int lane = threadIdx.x & 31, warp = threadIdx.x >> 5;
    int g = lane >> 2, tg = lane & 3;
    int m0 = warp * 16;

#pragma unroll
    for (int half = 0; half < 2; half++) {
        int gr = row0 + m0 + g + half * 8;
        if (gr < n) {
#pragma unroll
            for (int nt = 0; nt < 8; nt++) {
                int c = nt * 8 + 2 * tg;
                float v0 = acc[nt][half * 2 + 0] + s_b[c];
                float v1 = acc[nt][half * 2 + 1] + s_b[c + 1];
                *reinterpret_cast<float2*>(g_lin + gr * 64 + c) =
                    make_float2(v0, v1);
                g_lin_h[gr * 32 + (c >> 1)] = __floats2half2_rn(v0, v1);
            }
        }
    }
}

// ---------------------------------------------------------------------------
// 6) gather: warp per node, fp16 reads, fp32 accumulate
// ---------------------------------------------------------------------------
__global__ __launch_bounds__(256) void gather_kernel(int n, int E) {
    int w = (blockIdx.x * 256 + threadIdx.x) >> 5;
    int lane = threadIdx.x & 31;
    if (w >= n) return;

    int beg = g_off[w];
    int end = (w + 1 < n) ? g_off[w + 1] : E;

    float sx = 0.f, sy = 0.f;
    int j = beg;
    for (; j + 4 <= end; j += 4) {
        int s0 = g_elist[j];
        int s1 = g_elist[j + 1];
        int s2 = g_elist[j + 2];
        int s3 = g_elist[j + 3];
        float2 v0 = __half22float2(g_lin_h[s0 * 32 + lane]);
        float2 v1 = __half22float2(g_lin_h[s1 * 32 + lane]);
        float2 v2 = __half22float2(g_lin_h[s2 * 32 + lane]);
        float2 v3 = __half22float2(g_lin_h[s3 * 32 + lane]);
        sx += (v0.x + v1.x) + (v2.x + v3.x);
        sy += (v0.y + v1.y) + (v2.y + v3.y);
    }
    for (; j < end; j++) {
        float2 v = __half22float2(g_lin_h[g_elist[j] * 32 + lane]);
        sx += v.x;
        sy += v.y;
    }

    int deg = end - beg;
    float2 outv;
    if (deg > 0) {
        float inv = 1.f / (float)deg;
        float2 lv = *reinterpret_cast<const float2*>(g_lin + w * 64 + lane * 2);
        outv.x = lv.x - sx * inv;
        outv.y = lv.y - sy * inv;
    } else {
        outv = make_float2(0.f, 0.f);
    }
    reinterpret_cast<float2*>(g_lap + w * 64)[lane] = outv;
}

// ---------------------------------------------------------------------------
// 7) final: out = relu( merge @ W_tr^T + b_tr + lap )
// ---------------------------------------------------------------------------
__global__ __launch_bounds__(256) void final_kernel(
    const float* __restrict__ M, const float* __restrict__ W,
    const float* __restrict__ b, float* __restrict__ out, int n) {
    extern __shared__ float smem[];
    unsigned* s_x = reinterpret_cast<unsigned*>(smem);
    unsigned* s_w = reinterpret_cast<unsigned*>(smem + 128 * XS);
    float* s_b = smem + 128 * XS + 64 * XS;
    int row0 = blockIdx.x * 128;
    float acc[8][4];
    gemm_core_tc(M, W, b, n, row0, s_x, s_w, s_b, acc);

    int lane = threadIdx.x & 31, warp = threadIdx.x >> 5;
    int g = lane >> 2, tg = lane & 3;
    int m0 = warp * 16;

#pragma unroll
    for (int half = 0; half < 2; half++) {
        int gr = row0 + m0 + g + half * 8;
        if (gr < n) {
#pragma unroll
            for (int nt = 0; nt < 8; nt++) {
                int c = nt * 8 + 2 * tg;
                float2 lp = *reinterpret_cast<const float2*>(g_lap + gr * 64 + c);
                float v0 = fmaxf(acc[nt][half * 2 + 0] + s_b[c] + lp.x, 0.f);
                float v1 = fmaxf(acc[nt][half * 2 + 1] + s_b[c + 1] + lp.y, 0.f);
                *reinterpret_cast<float2*>(out + gr * 64 + c) =
                    make_float2(v0, v1);
            }
        }
    }
}

// ---------------------------------------------------------------------------
// Launch: 7 kernels.
// Inputs: data[N*64], merge[N*64], src_idx[E], tgt_idx[E],
//         W_lin[64*64], b_lin[64], W_tr[64*64], b_tr[64].  Output: float[N*64]
// ---------------------------------------------------------------------------
extern "C" void kernel_launch(void* const* d_in, const int* in_sizes, int n_in,
                              void* d_out, int out_size) {
    const float* data  = (const float*)d_in[0];
    const float* merge = (const float*)d_in[1];
    const int*   src   = (const int*)d_in[2];
    const int*   tgt   = (const int*)d_in[3];
    const float* W_lin = (const float*)d_in[4];
    const float* b_lin = (const float*)d_in[5];
    const float* W_tr  = (const float*)d_in[6];
    const float* b_tr  = (const float*)d_in[7];
    float* out = (float*)d_out;

    int n = in_sizes[0] / D;      // 50000
    int E = in_sizes[2];          // 800000
    int nchunk = (n + 1023) >> 10;

    size_t gemm_smem = GEMM_SMEM_FLOATS * sizeof(float);   // ~52.5 KB
    cudaFuncSetAttribute(gemm_lin_kernel,
                         cudaFuncAttributeMaxDynamicSharedMemorySize, (int)gemm_smem);
    cudaFuncSetAttribute(final_kernel,
                         cudaFuncAttributeMaxDynamicSharedMemorySize, (int)gemm_smem);

    int gemm_blocks = (n + 127) / 128;
    int edge4_blocks = ((E + 3) / 4 + 255) / 256;

    count_kernel<<<edge4_blocks, 256>>>(tgt, E);
    scanA_kernel<<<nchunk, 1024>>>(n);
    scanBC_kernel<<<(n + 255) / 256, 256>>>(n, nchunk);
    fill_kernel<<<edge4_blocks, 256>>>(src, tgt, E);
    gemm_lin_kernel<<<gemm_blocks, 256, gemm_smem>>>(data, W_lin, b_lin, n);
    gather_kernel<<<(n * 32 + 255) / 256, 256>>>(n, E);
    final_kernel<<<gemm_blocks, 256, gemm_smem>>>(merge, W_tr, b_tr, out, n);
}

// round 17
// speedup vs baseline: 1.3873x; 1.0208x over previous
#include <cuda_runtime.h>
#include <cuda_fp16.h>

#define MAX_NODES 50000
#define MAX_EDGES 800000
#define D 64

// ---------------------------------------------------------------------------
// Scratch (device globals; zero-initialized at load — g_deg invariant relies on it)
// ---------------------------------------------------------------------------
__device__ float   g_lin[MAX_NODES * D];       // data @ W_lin^T + b_lin (fp32)
__device__ __half2 g_lin_h[MAX_NODES * (D/2)]; // fp16 shadow for gather reads
__device__ float   g_lap[MAX_NODES * D];       // lin - (sum_src lin)/deg
__device__ int     g_deg[MAX_NODES];           // in-degree (zeroed by scanA each call)
__device__ int     g_off[MAX_NODES];           // CSR row offsets
__device__ int     g_rank[MAX_EDGES];          // per-edge rank within its target
__device__ int     g_csum[64];                 // per-chunk sums (<= 49 chunks)
__device__ int     g_elist[MAX_EDGES];         // src ids in CSR order

// ---------------------------------------------------------------------------
// 1) count in-degrees AND record each edge's rank within its target segment.
//    (the returned pre-increment value IS the CSR slot rank — fill needs no atomic)
// ---------------------------------------------------------------------------
__global__ void count_kernel(const int* __restrict__ tgt, int E) {
    int i = blockIdx.x * blockDim.x + threadIdx.x;
    int e = i * 4;
    if (e + 4 <= E) {
        int4 t4 = *reinterpret_cast<const int4*>(tgt + e);
        int4 r4;
        r4.x = atomicAdd(&g_deg[t4.x], 1);
        r4.y = atomicAdd(&g_deg[t4.y], 1);
        r4.z = atomicAdd(&g_deg[t4.z], 1);
        r4.w = atomicAdd(&g_deg[t4.w], 1);
        *reinterpret_cast<int4*>(g_rank + e) = r4;   // coalesced
    } else {
        for (; e < E; e++) g_rank[e] = atomicAdd(&g_deg[tgt[e]], 1);
    }
}

// ---------------------------------------------------------------------------
// 2) per-chunk exclusive scan (warp shuffles), zero g_deg, emit chunk sum
// ---------------------------------------------------------------------------
__global__ __launch_bounds__(1024) void scanA_kernel(int n) {
    __shared__ int sh_w[32];
    __shared__ int sh_total;
    int t = threadIdx.x, lane = t & 31, warp = t >> 5;
    int gid = blockIdx.x * 1024 + t;

    int v = 0;
    if (gid < n) {
        v = g_deg[gid];
        g_deg[gid] = 0;
    }
    int val = v;
#pragma unroll
    for (int s = 1; s < 32; s <<= 1) {
        int u = __shfl_up_sync(0xffffffffu, val, s);
        if (lane >= s) val += u;
    }
    if (lane == 31) sh_w[warp] = val;
    __syncthreads();
    if (warp == 0) {
        int wv = sh_w[lane];
        int wi = wv;
#pragma unroll
        for (int s = 1; s < 32; s <<= 1) {
            int u = __shfl_up_sync(0xffffffffu, wi, s);
            if (lane >= s) wi += u;
        }
        sh_w[lane] = wi - wv;
        if (lane == 31) sh_total = wi;
    }
    __syncthreads();
    if (gid < n) g_off[gid] = (val - v) + sh_w[warp];
    if (t == 0) g_csum[blockIdx.x] = sh_total;   // single writer
}

// ---------------------------------------------------------------------------
// 3) add chunk prefix (redundant per-block 64-wide scan) -> final g_off
// ---------------------------------------------------------------------------
__global__ __launch_bounds__(256) void scanBC_kernel(int n, int nchunk) {
    __shared__ int sh[64];
    int t = threadIdx.x;
    if (t < 64) sh[t] = (t < nchunk) ? g_csum[t] : 0;
    __syncthreads();
#pragma unroll
    for (int s = 1; s < 64; s <<= 1) {
        int a = (t >= s && t < 64) ? sh[t - s] : 0;
        __syncthreads();
        if (t < 64) sh[t] += a;
        __syncthreads();
    }
    int i = blockIdx.x * 256 + t;
    if (i < n) {
        int c = i >> 10;
        int coff = (c > 0) ? sh[c - 1] : 0;
        g_off[i] += coff;
    }
}

// ---------------------------------------------------------------------------
// 4) fill CSR edge list — ATOMIC-FREE: slot = off[tgt] + rank[e]
// ---------------------------------------------------------------------------
__global__ void fill_kernel(const int* __restrict__ src,
                            const int* __restrict__ tgt, int E) {
    int i = blockIdx.x * blockDim.x + threadIdx.x;
    int e = i * 4;
    if (e + 4 <= E) {
        int4 t4 = *reinterpret_cast<const int4*>(tgt + e);
        int4 s4 = *reinterpret_cast<const int4*>(src + e);
        int4 r4 = *reinterpret_cast<const int4*>(g_rank + e);
        int p0 = g_off[t4.x] + r4.x;
        int p1 = g_off[t4.y] + r4.y;
        int p2 = g_off[t4.z] + r4.z;
        int p3 = g_off[t4.w] + r4.w;
        g_elist[p0] = s4.x;
        g_elist[p1] = s4.y;
        g_elist[p2] = s4.z;
        g_elist[p3] = s4.w;
    } else {
        for (; e < E; e++) {
            g_elist[g_off[tgt[e]] + g_rank[e]] = src[e];
        }
    }
}

// ---------------------------------------------------------------------------
// tf32 tensor-core GEMM: OUT[128x64] = X[128x64] @ W[64x64]^T  per block.
// ---------------------------------------------------------------------------
#define XS 68
#define GEMM_SMEM_FLOATS (128 * XS + 64 * XS + 64)   // ~52.5 KB

__device__ __forceinline__ unsigned f2tf32(float f) {
    unsigned u;
    asm("cvt.rna.tf32.f32 %0, %1;" : "=r"(u) : "f"(f));
    return u;
}

__device__ __forceinline__ void mma_tf32(float c[4], const unsigned a[4],
                                         const unsigned b[2]) {
    asm volatile(
        "mma.sync.aligned.m16n8k8.row.col.f32.tf32.tf32.f32 "
        "{%0,%1,%2,%3}, {%4,%5,%6,%7}, {%8,%9}, {%0,%1,%2,%3};"
        : "+f"(c[0]), "+f"(c[1]), "+f"(c[2]), "+f"(c[3])
        : "r"(a[0]), "r"(a[1]), "r"(a[2]), "r"(a[3]), "r"(b[0]), "r"(b[1]));
}

__device__ __forceinline__ void gemm_core_tc(
    const float* __restrict__ X, const float* __restrict__ W,
    const float* __restrict__ b, int n, int row0,
    unsigned* s_x, unsigned* s_w, float* s_b, float acc[8][4]) {
    int t = threadIdx.x;
    for (int i = t; i < 128 * 64; i += 256) {
        int r = i >> 6, k = i & 63;
        int gr = row0 + r;
        s_x[r * XS + k] = (gr < n) ? f2tf32(X[gr * 64 + k]) : 0u;
    }
    for (int i = t; i < 64 * 64; i += 256) {
        int c = i >> 6, k = i & 63;
        s_w[c * XS + k] = f2tf32(W[c * 64 + k]);
    }
    if (t < 64) s_b[t] = b[t];
    __syncthreads();

    int lane = t & 31, warp = t >> 5;
    int g = lane >> 2, tg = lane & 3;
    int m0 = warp * 16;

#pragma unroll
    for (int nt = 0; nt < 8; nt++)
#pragma unroll
        for (int j = 0; j < 4; j++) acc[nt][j] = 0.f;

#pragma unroll
    for (int ks = 0; ks < 8; ks++) {
        int k0 = ks * 8;
        unsigned a[4];
        a[0] = s_x[(m0 + g) * XS + k0 + tg];
        a[1] = s_x[(m0 + g + 8) * XS + k0 + tg];
        a[2] = s_x[(m0 + g) * XS + k0 + tg + 4];
        a[3] = s_x[(m0 + g + 8) * XS + k0 + tg + 4];
#pragma unroll
        for (int nt = 0; nt < 8; nt++) {
            unsigned bb[2];
            int nn = nt * 8 + g;
            bb[0] = s_w[nn * XS + k0 + tg];
            bb[1] = s_w[nn * XS + k0 + tg + 4];
            mma_tf32(acc[nt], a, bb);
        }
    }
}

// ---------------------------------------------------------------------------
// 5) GEMM 1: g_lin = data @ W_lin^T + b_lin  (+ packed fp16 shadow)
// ---------------------------------------------------------------------------
__global__ __launch_bounds__(256) void gemm_lin_kernel(
    const float* __restrict__ X, const float* __restrict__ W,
    const float* __restrict__ b, int n) {
    extern __shared__ float smem[];
    unsigned* s_x = reinterpret_cast<unsigned*>(smem);
    unsigned* s_w = reinterpret_cast<unsigned*>(smem + 128 * XS);
    float* s_b = smem + 128 * XS + 64 * XS;
    int row0 = blockIdx.x * 128;
    float acc[8][4];
    gemm_core_tc(X, W, b, n, row0, s_x, s_w, s_b, acc);

    int lane = threadIdx.x & 31, warp = threadIdx.x >> 5;
    int g = lane >> 2, tg = lane & 3;
    int m0 = warp * 16;

#pragma unroll
    for (int half = 0; half < 2; half++) {
        int gr = row0 + m0 + g + half * 8;
        if (gr < n) {
#pragma unroll
            for (int nt = 0; nt < 8; nt++) {
                int c = nt * 8 + 2 * tg;
                float v0 = acc[nt][half * 2 + 0] + s_b[c];
                float v1 = acc[nt][half * 2 + 1] + s_b[c + 1];
                *reinterpret_cast<float2*>(g_lin + gr * 64 + c) =
                    make_float2(v0, v1);
                g_lin_h[gr * 32 + (c >> 1)] = __floats2half2_rn(v0, v1);
            }
        }
    }
}

// ---------------------------------------------------------------------------
// 6) gather: warp per node, fp16 reads, fp32 accumulate
// ---------------------------------------------------------------------------
__global__ __launch_bounds__(256) void gather_kernel(int n, int E) {
    int w = (blockIdx.x * 256 + threadIdx.x) >> 5;
    int lane = threadIdx.x & 31;
    if (w >= n) return;

    int beg = g_off[w];
    int end = (w + 1 < n) ? g_off[w + 1] : E;

    float sx = 0.f, sy = 0.f;
    int j = beg;
    for (; j + 4 <= end; j += 4) {
        int s0 = g_elist[j];
        int s1 = g_elist[j + 1];
        int s2 = g_elist[j + 2];
        int s3 = g_elist[j + 3];
        float2 v0 = __half22float2(g_lin_h[s0 * 32 + lane]);
        float2 v1 = __half22float2(g_lin_h[s1 * 32 + lane]);
        float2 v2 = __half22float2(g_lin_h[s2 * 32 + lane]);
        float2 v3 = __half22float2(g_lin_h[s3 * 32 + lane]);
        sx += (v0.x + v1.x) + (v2.x + v3.x);
        sy += (v0.y + v1.y) + (v2.y + v3.y);
    }
    for (; j < end; j++) {
        float2 v = __half22float2(g_lin_h[g_elist[j] * 32 + lane]);
        sx += v.x;
        sy += v.y;
    }

    int deg = end - beg;
    float2 outv;
    if (deg > 0) {
        float inv = 1.f / (float)deg;
        float2 lv = *reinterpret_cast<const float2*>(g_lin + w * 64 + lane * 2);
        outv.x = lv.x - sx * inv;
        outv.y = lv.y - sy * inv;
    } else {
        outv = make_float2(0.f, 0.f);
    }
    reinterpret_cast<float2*>(g_lap + w * 64)[lane] = outv;
}

// ---------------------------------------------------------------------------
// 7) final: out = relu( merge @ W_tr^T + b_tr + lap )
// ---------------------------------------------------------------------------
__global__ __launch_bounds__(256) void final_kernel(
    const float* __restrict__ M, const float* __restrict__ W,
    const float* __restrict__ b, float* __restrict__ out, int n) {
    extern __shared__ float smem[];
    unsigned* s_x = reinterpret_cast<unsigned*>(smem);
    unsigned* s_w = reinterpret_cast<unsigned*>(smem + 128 * XS);
    float* s_b = smem + 128 * XS + 64 * XS;
    int row0 = blockIdx.x * 128;
    float acc[8][4];
    gemm_core_tc(M, W, b, n, row0, s_x, s_w, s_b, acc);

    int lane = threadIdx.x & 31, warp = threadIdx.x >> 5;
    int g = lane >> 2, tg = lane & 3;
    int m0 = warp * 16;

#pragma unroll
    for (int half = 0; half < 2; half++) {
        int gr = row0 + m0 + g + half * 8;
        if (gr < n) {
#pragma unroll
            for (int nt = 0; nt < 8; nt++) {
                int c = nt * 8 + 2 * tg;
                float2 lp = *reinterpret_cast<const float2*>(g_lap + gr * 64 + c);
                float v0 = fmaxf(acc[nt][half * 2 + 0] + s_b[c] + lp.x, 0.f);
                float v1 = fmaxf(acc[nt][half * 2 + 1] + s_b[c + 1] + lp.y, 0.f);
                *reinterpret_cast<float2*>(out + gr * 64 + c) =
                    make_float2(v0, v1);
            }
        }
    }
}

// ---------------------------------------------------------------------------
// Launch: 7 kernels.
// Inputs: data[N*64], merge[N*64], src_idx[E], tgt_idx[E],
//         W_lin[64*64], b_lin[64], W_tr[64*64], b_tr[64].  Output: float[N*64]
// ---------------------------------------------------------------------------
extern "C" void kernel_launch(void* const* d_in, const int* in_sizes, int n_in,
                              void* d_out, int out_size) {
    const float* data  = (const float*)d_in[0];
    const float* merge = (const float*)d_in[1];
    const int*   src   = (const int*)d_in[2];
    const int*   tgt   = (const int*)d_in[3];
    const float* W_lin = (const float*)d_in[4];
    const float* b_lin = (const float*)d_in[5];
    const float* W_tr  = (const float*)d_in[6];
    const float* b_tr  = (const float*)d_in[7];
    float* out = (float*)d_out;

    int n = in_sizes[0] / D;      // 50000
    int E = in_sizes[2];          // 800000
    int nchunk = (n + 1023) >> 10;

    size_t gemm_smem = GEMM_SMEM_FLOATS * sizeof(float);   // ~52.5 KB
    cudaFuncSetAttribute(gemm_lin_kernel,
                         cudaFuncAttributeMaxDynamicSharedMemorySize, (int)gemm_smem);
    cudaFuncSetAttribute(final_kernel,
                         cudaFuncAttributeMaxDynamicSharedMemorySize, (int)gemm_smem);

    int gemm_blocks = (n + 127) / 128;
    int edge4_blocks = ((E + 3) / 4 + 255) / 256;

    count_kernel<<<edge4_blocks, 256>>>(tgt, E);
    scanA_kernel<<<nchunk, 1024>>>(n);
    scanBC_kernel<<<(n + 255) / 256, 256>>>(n, nchunk);
    fill_kernel<<<edge4_blocks, 256>>>(src, tgt, E);
    gemm_lin_kernel<<<gemm_blocks, 256, gemm_smem>>>(data, W_lin, b_lin, n);
    gather_kernel<<<(n * 32 + 255) / 256, 256>>>(n, E);
    final_kernel<<<gemm_blocks, 256, gemm_smem>>>(merge, W_tr, b_tr, out, n);
}